// round 8
// baseline (speedup 1.0000x reference)
#include <cuda_runtime.h>
#include <cuda_bf16.h>
#include <cstdint>

typedef unsigned int u32;

#define D        512
#define BDIM     1024
#define C        200
#define NKEYS    50000
#define BM       64
#define BN       128
#define NTILES   391
#define NPAD     (NTILES * BN)
#define BTILES   (BDIM / BM)          // 16
#define NGROUPS  9                    // 144 CTAs = one wave
#define NSTAGES  4
#define NTHREADS 512
#define SB       72                   // B stage row stride (bf16)
#define SAQ      520                  // A panel row stride (bf16)
#define CP       201                  // csh row stride (floats)
#define SS       130                  // staging row stride (floats)

#define BS_BYTES (BN * SB * 2)                 // 18432
#define OFF_BS   0
#define OFF_AS   (NSTAGES * BS_BYTES)          // 73728
#define OFF_CSH  (OFF_AS + BM * SAQ * 2)       // 140288
#define OFF_LABS (OFF_CSH + BM * CP * 4)       // 191744
#define OFF_SIM  (OFF_LABS + BN * 4)           // 192256
#define SMEM_DYN (OFF_SIM + BM * SS * 4)       // 225536

// ---------------- device scratch ----------------
__device__ __align__(16) __nv_bfloat16 g_qbf[BDIM][D];
__device__ float g_qf[BDIM * D];
__device__ float g_tf[C * D];
__device__ __align__(16) __nv_bfloat16 g_kbf[NPAD][D];   // label-sorted; tail rows zero
__device__ int   g_lab[NPAD];                            // sorted labels
__device__ int   g_hist[C];
__device__ int   g_cur[C];
__device__ float g_part[NGROUPS * BDIM * C];

// ---------------- helpers ----------------
__device__ __forceinline__ u32 smem_u32(const void* p) {
    u32 a;
    asm("{ .reg .u64 t; cvta.to.shared.u64 t, %1; cvt.u32.u64 %0, t; }" : "=r"(a) : "l"(p));
    return a;
}

__device__ __forceinline__ void ldmx4(u32& r0, u32& r1, u32& r2, u32& r3, const void* p) {
    u32 addr = smem_u32(p);
    asm volatile("ldmatrix.sync.aligned.m8n8.x4.shared.b16 {%0,%1,%2,%3}, [%4];\n"
                 : "=r"(r0), "=r"(r1), "=r"(r2), "=r"(r3) : "r"(addr));
}

__device__ __forceinline__ void mma_bf16(float* d, const u32* a, const u32* b) {
    asm volatile(
        "mma.sync.aligned.m16n8k16.row.col.f32.bf16.bf16.f32 "
        "{%0,%1,%2,%3}, {%4,%5,%6,%7}, {%8,%9}, {%0,%1,%2,%3};\n"
        : "+f"(d[0]), "+f"(d[1]), "+f"(d[2]), "+f"(d[3])
        : "r"(a[0]), "r"(a[1]), "r"(a[2]), "r"(a[3]), "r"(b[0]), "r"(b[1]));
}

__device__ __forceinline__ void cp16(u32 dst, const void* src) {
    asm volatile("cp.async.cg.shared.global [%0], [%1], 16;" :: "r"(dst), "l"(src));
}
#define CP_COMMIT() asm volatile("cp.async.commit_group;" ::: "memory")
#define CP_WAIT3()  asm volatile("cp.async.wait_group 3;" ::: "memory")

// ---------------- prep ----------------
__global__ void prep_zero() {
    int i = threadIdx.x;
    if (i < C) g_hist[i] = 0;
}

__global__ void prep_hist(const int* __restrict__ labels) {
    int i = blockIdx.x * blockDim.x + threadIdx.x;
    if (i < NKEYS) {
        int l = labels[i];
        l = (l < 0) ? 0 : ((l >= C) ? C - 1 : l);
        atomicAdd(&g_hist[l], 1);
    }
}

__global__ void prep_scan() {
    __shared__ int sh[C];
    int t = threadIdx.x;
    if (t < C) sh[t] = g_hist[t];
    __syncthreads();
    if (t == 0) {
        int acc = 0;
        for (int c = 0; c < C; c++) { int v = sh[c]; sh[c] = acc; acc += v; }
    }
    __syncthreads();
    if (t < C) g_cur[t] = sh[t];
}

__device__ __forceinline__ float blk_sumsq(float4 x) {
    int t = threadIdx.x;
    float ss = x.x * x.x + x.y * x.y + x.z * x.z + x.w * x.w;
#pragma unroll
    for (int o = 16; o; o >>= 1) ss += __shfl_xor_sync(0xffffffffu, ss, o);
    __shared__ float ws[4];
    if ((t & 31) == 0) ws[t >> 5] = ss;
    __syncthreads();
    return ws[0] + ws[1] + ws[2] + ws[3];
}

__global__ void prep_q(const float* __restrict__ img) {
    int row = blockIdx.x, t = threadIdx.x;
    float4 x = ((const float4*)(img + row * D))[t];
    float inv = rsqrtf(blk_sumsq(x));
    float4 y = make_float4(x.x * inv, x.y * inv, x.z * inv, x.w * inv);
    ((float4*)(g_qf + row * D))[t] = y;
    __nv_bfloat162* dst = (__nv_bfloat162*)&g_qbf[row][0];
    dst[2 * t + 0] = __floats2bfloat162_rn(y.x, y.y);
    dst[2 * t + 1] = __floats2bfloat162_rn(y.z, y.w);
}

__global__ void prep_t(const float* __restrict__ txt) {
    int row = blockIdx.x, t = threadIdx.x;
    float4 x = ((const float4*)(txt + row * D))[t];
    float inv = rsqrtf(blk_sumsq(x));
    ((float4*)(g_tf + row * D))[t] = make_float4(x.x * inv, x.y * inv, x.z * inv, x.w * inv);
}

// normalize + counting-sort scatter by label
__global__ void prep_k(const float* __restrict__ keys, const int* __restrict__ labels) {
    __shared__ int spos;
    int row = blockIdx.x, t = threadIdx.x;
    if (t == 0) {
        int l = labels[row];
        l = (l < 0) ? 0 : ((l >= C) ? C - 1 : l);
        int p = atomicAdd(&g_cur[l], 1);
        g_lab[p] = l;
        spos = p;
    }
    float4 x = ((const float4*)(keys + row * D))[t];
    float inv = rsqrtf(blk_sumsq(x));   // __syncthreads inside publishes spos
    int p = spos;
    __nv_bfloat162* dst = (__nv_bfloat162*)&g_kbf[p][0];
    dst[2 * t + 0] = __floats2bfloat162_rn(x.x * inv, x.y * inv);
    dst[2 * t + 1] = __floats2bfloat162_rn(x.z * inv, x.w * inv);
}

// ---------------- main: pipelined HMMA GEMM + run-scatter epilogue ----------------
extern __shared__ unsigned char smraw[];

__global__ void __launch_bounds__(NTHREADS, 1) gemm_scatter() {
    __nv_bfloat16* As = (__nv_bfloat16*)(smraw + OFF_AS);
    float* csh  = (float*)(smraw + OFF_CSH);
    int*   labs = (int*)(smraw + OFF_LABS);
    float* ssim = (float*)(smraw + OFF_SIM);

    int tid = threadIdx.x;
    int lane = tid & 31, wid = tid >> 5;
    int wm = wid >> 2, wn = wid & 3;      // 4 x 4 warps, warp tile 16x32
    int bt = blockIdx.x;
    int ng = blockIdx.y;

    for (int i = tid; i < BM * CP; i += NTHREADS) csh[i] = 0.f;

    // group 0: A panel 64 x 512 bf16
    {
        u32 asb = smem_u32(As);
        const char* src = (const char*)&g_qbf[bt * BM][0];
#pragma unroll
        for (int k = 0; k < 8; k++) {
            int idx = tid + k * NTHREADS;     // 0..4095
            int r = idx >> 6, c = idx & 63;
            cp16(asb + (u32)(r * (SAQ * 2) + c * 16), src + r * (D * 2) + c * 16);
        }
        CP_COMMIT();
    }

    int nt = (NTILES - 1 - ng) / NGROUPS + 1;   // strided tiles: ng, ng+9, ...
    int nchunks = nt * 8;
    u32 bsb = smem_u32(smraw + OFF_BS);

    // prologue: chunks 0..2
    for (int p = 0; p < 3; p++) {
        int tloc = p >> 3, ch = p & 7;
        int n0 = (ng + tloc * NGROUPS) * BN;
        u32 sb = bsb + (u32)(p % NSTAGES) * BS_BYTES;
        const char* src = (const char*)&g_kbf[n0][0] + ch * 128;
#pragma unroll
        for (int k = 0; k < 2; k++) {
            int idx = tid + k * NTHREADS;     // 0..1023
            int r = idx >> 3, s = idx & 7;
            cp16(sb + (u32)(r * (SB * 2) + s * 16), src + r * (D * 2) + s * 16);
        }
        CP_COMMIT();
    }

    float acc[4][4];
#pragma unroll
    for (int ni = 0; ni < 4; ni++)
#pragma unroll
        for (int e = 0; e < 4; e++) acc[ni][e] = 0.f;

    for (int g = 0; g < nchunks; g++) {
        __syncthreads();                      // stage (g+3)%4 free to overwrite
        int pf = g + 3;
        if (pf < nchunks) {
            int tloc = pf >> 3, ch = pf & 7;
            int n0 = (ng + tloc * NGROUPS) * BN;
            u32 sb = bsb + (u32)(pf % NSTAGES) * BS_BYTES;
            const char* src = (const char*)&g_kbf[n0][0] + ch * 128;
#pragma unroll
            for (int k = 0; k < 2; k++) {
                int idx = tid + k * NTHREADS;
                int r = idx >> 3, s = idx & 7;
                cp16(sb + (u32)(r * (SB * 2) + s * 16), src + r * (D * 2) + s * 16);
            }
        }
        CP_COMMIT();
        CP_WAIT3();                           // chunk g (and A panel) resident
        __syncthreads();

        int ch = g & 7;
        if (ch == 0 && tid < BN) {
            int n0 = (ng + (g >> 3) * NGROUPS) * BN;
            labs[tid] = g_lab[n0 + tid];      // sorted labels
        }

        __nv_bfloat16* Bst = (__nv_bfloat16*)(smraw + OFF_BS + (g % NSTAGES) * BS_BYTES);
#pragma unroll
        for (int ks = 0; ks < 4; ks++) {
            int kk = ks * 16;
            u32 afr[4];
            {
                int rA = wm * 16 + (lane & 7) + ((lane >> 3) & 1) * 8;
                int kA = ch * 64 + kk + ((lane >> 4) & 1) * 8;
                ldmx4(afr[0], afr[1], afr[2], afr[3], As + rA * SAQ + kA);
            }
            u32 bfr[4][2];
#pragma unroll
            for (int gg = 0; gg < 2; gg++) {
                int rB = wn * 32 + gg * 16 + (lane & 7) + ((lane >> 4) & 1) * 8;
                int kB = kk + ((lane >> 3) & 1) * 8;
                u32 r0, r1, r2, r3;
                ldmx4(r0, r1, r2, r3, Bst + rB * SB + kB);
                bfr[gg * 2 + 0][0] = r0; bfr[gg * 2 + 0][1] = r1;
                bfr[gg * 2 + 1][0] = r2; bfr[gg * 2 + 1][1] = r3;
            }
#pragma unroll
            for (int ni = 0; ni < 4; ni++)
                mma_bf16(acc[ni], afr, bfr[ni]);
        }

        if (ch == 7) {                        // tile done: stage sims, then run-scan
            int n0 = (ng + (g >> 3) * NGROUPS) * BN;
            int rb = wm * 16 + (lane >> 2);
#pragma unroll
            for (int ni = 0; ni < 4; ni++) {
                int cb = wn * 32 + ni * 8 + 2 * (lane & 3);
                *(float2*)&ssim[rb * SS + cb]       = make_float2(acc[ni][0], acc[ni][1]);
                *(float2*)&ssim[(rb + 8) * SS + cb] = make_float2(acc[ni][2], acc[ni][3]);
                acc[ni][0] = acc[ni][1] = acc[ni][2] = acc[ni][3] = 0.f;
            }
            __syncthreads();
            // run-accumulate: thread owns row r, 16-col segment; labels sorted
            int r = tid >> 3, seg = tid & 7;
            int vc = NKEYS - n0; if (vc > BN) vc = BN;
            const float* srow = ssim + r * SS + seg * 16;
            float run = 0.f; int cur = -1;
#pragma unroll
            for (int i = 0; i < 16; i++) {
                int c = seg * 16 + i;
                if (c < vc) {
                    int lab = labs[c];
                    float v = __expf(5.0f * srow[i]);
                    if (lab != cur) {
                        if (cur >= 0) atomicAdd(&csh[r * CP + cur], run);
                        cur = lab; run = 0.f;
                    }
                    run += v;
                }
            }
            if (cur >= 0) atomicAdd(&csh[r * CP + cur], run);
        }
    }

    __syncthreads();
    float* dst = g_part + ((size_t)ng * BDIM + bt * BM) * C;
    for (int i = tid; i < BM * C; i += NTHREADS) {
        int r = i / C, c = i % C;
        dst[i] = csh[r * CP + c];
    }
}

// ---------------- z branch + combine partials ----------------
__global__ void __launch_bounds__(256) zcombine(float* __restrict__ out) {
    __shared__ float a2[64][17];
    __shared__ float b2[64][17];
    int tid = threadIdx.x;
    int tx = tid & 15, ty = tid >> 4;
    int rb = blockIdx.x * 64, cb = blockIdx.y * 64;

    float acc[4][4];
#pragma unroll
    for (int i = 0; i < 4; i++)
#pragma unroll
        for (int j = 0; j < 4; j++) acc[i][j] = 0.f;

    for (int k0 = 0; k0 < D; k0 += 16) {
        __syncthreads();
#pragma unroll
        for (int j = 0; j < 4; j++) {
            int idx = tid + j * 256;
            int r = idx >> 4, c = idx & 15;
            a2[r][c] = g_qf[(rb + r) * D + k0 + c];
            int cls = cb + r;
            b2[r][c] = (cls < C) ? g_tf[cls * D + k0 + c] : 0.f;
        }
        __syncthreads();
#pragma unroll
        for (int k = 0; k < 16; k++) {
            float av[4], bv[4];
#pragma unroll
            for (int i = 0; i < 4; i++) { av[i] = a2[ty * 4 + i][k]; bv[i] = b2[tx * 4 + i][k]; }
#pragma unroll
            for (int i = 0; i < 4; i++)
#pragma unroll
                for (int j = 0; j < 4; j++) acc[i][j] += av[i] * bv[j];
        }
    }

#pragma unroll
    for (int i = 0; i < 4; i++)
#pragma unroll
        for (int j = 0; j < 4; j++) {
            int r = rb + ty * 4 + i, c = cb + tx * 4 + j;
            if (c < C) {
                float s = 0.f;
#pragma unroll
                for (int gg = 0; gg < NGROUPS; gg++)
                    s += g_part[((size_t)gg * BDIM + r) * C + c];
                out[r * C + c] = 50.f * acc[i][j] + 0.5f * s;
            }
        }
}

// ---------------- launch ----------------
extern "C" void kernel_launch(void* const* d_in, const int* in_sizes, int n_in,
                              void* d_out, int out_size) {
    const float* img  = (const float*)d_in[0];
    const float* txt  = (const float*)d_in[1];
    const float* keys = (const float*)d_in[2];
    const int*   labs = (const int*)d_in[3];
    float* out = (float*)d_out;

    cudaFuncSetAttribute(gemm_scatter, cudaFuncAttributeMaxDynamicSharedMemorySize,
                         SMEM_DYN);

    prep_zero<<<1, 256>>>();
    prep_hist<<<(NKEYS + 255) / 256, 256>>>(labs);
    prep_scan<<<1, 256>>>();
    prep_q<<<BDIM, 128>>>(img);
    prep_t<<<C, 128>>>(txt);
    prep_k<<<NKEYS, 128>>>(keys, labs);
    gemm_scatter<<<dim3(BTILES, NGROUPS), NTHREADS, SMEM_DYN>>>();
    zcombine<<<dim3(BDIM / 64, 4), 256>>>(out);
}